// round 6
// baseline (speedup 1.0000x reference)
#include <cuda_runtime.h>
#include <cstdint>

// Painting: sequential alpha-composite of N=128 RGBA layers onto a ones canvas.
// canvas = canvas*(1-a) + a*poly, a = poly[alpha]*0.8, per-pixel recurrence.
//
// R6: warp-autonomous cp.async pipeline, DEPTH=3 (was 4). 24KB smem/block ->
// 8 blocks/SM (64 warps, full occupancy) -> all 1024 blocks resident in ONE
// wave. R5's 32KB footprint allowed only 6 blocks/SM = 888 resident, leaving
// a 136-block second wave that ran at ~1 block/SM and starved DRAM.
// Depth 3 still gives ~128KB in flight per SM, far past the latency-BW knee.

#define OPACITY 0.8f
#define HW        262144            // 512*512
#define NLAYERS   128
#define LPS       2                 // layers per stage
#define DEPTH     3                 // pipeline depth (stages in flight)
#define NSTAGES   (NLAYERS / LPS)   // 64
#define WARP_STAGE_FLOATS (LPS * 4 * 32)   // 256 floats = 1KB

__device__ __forceinline__ void cp_async16(uint32_t smem_addr, const void* gptr)
{
    asm volatile("cp.async.cg.shared.global [%0], [%1], 16;\n"
                 :: "r"(smem_addr), "l"(gptr));
}
__device__ __forceinline__ void cp_commit()
{
    asm volatile("cp.async.commit_group;\n" ::: "memory");
}
__device__ __forceinline__ void cp_wait_oldest()
{
    asm volatile("cp.async.wait_group %0;\n" :: "n"(DEPTH - 1) : "memory");
}

__global__ __launch_bounds__(256)
void painting_kernel(const float* __restrict__ polys,
                     float* __restrict__ out)
{
    // [warp][stage][layer-in-stage][channel][32 floats] = 8*3*1KB = 24KB
    __shared__ float sbuf[8][DEPTH][WARP_STAGE_FLOATS];

    const int t    = threadIdx.x;
    const int w    = t >> 5;
    const int lane = t & 31;
    const int pix0 = blockIdx.x * 256 + w * 32;   // this warp's 32 pixels

    // loader role: lane l fetches channel (l>>3), 16B chunk (l&7) of the
    // warp's 128B line for that channel.
    const int lc   = lane >> 3;          // channel 0..3
    const int foff = (lane & 7) * 4;     // float offset within 32

    const float* gbase = polys + (size_t)lc * HW + pix0 + foff;

    auto issue_stage = [&](int stage_idx, int slot) {
        uint32_t sm = (uint32_t)__cvta_generic_to_shared(&sbuf[w][slot][0])
                      + (uint32_t)(lc * 32 + foff) * 4u;
#pragma unroll
        for (int u = 0; u < LPS; ++u) {
            int l = stage_idx * LPS + u;
            cp_async16(sm + u * (4 * 32 * 4),          // +512B per layer
                       gbase + (size_t)l * (4 * HW));
        }
    };

    // ---- prologue: fill the pipe ----
#pragma unroll
    for (int k = 0; k < DEPTH; ++k) {
        issue_stage(k, k);
        cp_commit();
    }

    float c0 = 1.f, c1 = 1.f, c2 = 1.f, c3 = 1.f;

    int slot = 0;
    for (int s = 0; s < NSTAGES; ++s) {
        cp_wait_oldest();    // oldest pending stage complete (per-lane groups)
        __syncwarp();        // publish across the warp's lanes

        const float* buf = &sbuf[w][slot][0];
#pragma unroll
        for (int u = 0; u < LPS; ++u) {
            const float* lb = buf + u * 128;
            float p0 = lb[lane];
            float p1 = lb[32 + lane];
            float p2 = lb[64 + lane];
            float p3 = lb[96 + lane];
            float a  = p3 * OPACITY;
            c0 = fmaf(a, p0 - c0, c0);
            c1 = fmaf(a, p1 - c1, c1);
            c2 = fmaf(a, p2 - c2, c2);
            c3 = fmaf(a, p3 - c3, c3);
        }
        __syncwarp();        // all lanes done reading slot before refill

        int ns = s + DEPTH;
        if (ns < NSTAGES)
            issue_stage(ns, slot);
        cp_commit();         // (possibly empty) group keeps wait count aligned

        slot = (slot == DEPTH - 1) ? 0 : slot + 1;
    }

    int p = pix0 + lane;
    out[p]          = c0;
    out[HW + p]     = c1;
    out[2 * HW + p] = c2;
    out[3 * HW + p] = c3;
}

extern "C" void kernel_launch(void* const* d_in, const int* in_sizes, int n_in,
                              void* d_out, int out_size)
{
    const float* polys = (const float*)d_in[0];
    float* out = (float*)d_out;

    const int blocks = HW / 256;   // 1024
    painting_kernel<<<blocks, 256>>>(polys, out);
}

// round 7
// speedup vs baseline: 1.0615x; 1.0615x over previous
#include <cuda_runtime.h>
#include <cstdint>

// Painting: sequential alpha-composite of N=128 RGBA layers onto a ones canvas.
// canvas = canvas*(1-a) + a*poly, a = poly[alpha]*0.8, per-pixel recurrence.
//
// R7: fully thread-private cp.async pipeline — zero synchronization.
// Each thread owns 4 consecutive pixels; per layer it issues 4x cp.async.cg
// 16B (one per channel plane, exactly the bytes it will consume), so stage
// completion needs only the thread's own cp.async.wait_group. No __syncwarp,
// no __syncthreads, no cross-lane data sharing.
// 64-thread blocks -> 1024 blocks over 148 SMs (avg 6.92, max 7): <2%
// imbalance. smem [stage][chan][thread] keeps cp.async stores and LDS.128
// reads conflict-free. Depth 4 => ~84KB in flight per SM.

#define OPACITY 0.8f
#define HW      262144              // 512*512
#define NLAYERS 128
#define DEPTH   4                   // stages (1 layer per stage)
#define TPB     64

__device__ __forceinline__ void cp_async16(uint32_t smem_addr, const void* gptr)
{
    asm volatile("cp.async.cg.shared.global [%0], [%1], 16;\n"
                 :: "r"(smem_addr), "l"(gptr));
}
__device__ __forceinline__ void cp_commit()
{
    asm volatile("cp.async.commit_group;\n" ::: "memory");
}
__device__ __forceinline__ void cp_wait_oldest()
{
    asm volatile("cp.async.wait_group %0;\n" :: "n"(DEPTH - 1) : "memory");
}

__global__ __launch_bounds__(TPB)
void painting_kernel(const float* __restrict__ polys,
                     float* __restrict__ out)
{
    // [stage][channel][thread] float4 : 4*4*64*16B = 16KB
    __shared__ float4 sbuf[DEPTH][4][TPB];

    const int t = threadIdx.x;
    const int q = (blockIdx.x * TPB + t) * 4;   // first of this thread's 4 pixels

    const float* gbase = polys + q;             // + (l*4+c)*HW per layer/channel

    const uint32_t smem0 = (uint32_t)__cvta_generic_to_shared(&sbuf[0][0][t]);
    // address of sbuf[slot][c][t] = smem0 + (slot*4 + c) * (TPB*16)

    auto issue_layer = [&](int l, int slot) {
#pragma unroll
        for (int c = 0; c < 4; ++c) {
            cp_async16(smem0 + (uint32_t)(slot * 4 + c) * (TPB * 16),
                       gbase + (size_t)(l * 4 + c) * HW);
        }
        cp_commit();
    };

    // ---- prologue: fill the pipe ----
#pragma unroll
    for (int k = 0; k < DEPTH; ++k)
        issue_layer(k, k);

    float4 c0 = make_float4(1.f, 1.f, 1.f, 1.f);
    float4 c1 = c0, c2 = c0, c3 = c0;

    int slot = 0;
    for (int l = 0; l < NLAYERS; ++l) {
        cp_wait_oldest();   // this thread's oldest stage is complete; the
                            // thread reads only its own cp.async results, so
                            // no warp/block sync is required.

        float4 p0 = sbuf[slot][0][t];
        float4 p1 = sbuf[slot][1][t];
        float4 p2 = sbuf[slot][2][t];
        float4 p3 = sbuf[slot][3][t];

        float ax = p3.x * OPACITY;
        float ay = p3.y * OPACITY;
        float az = p3.z * OPACITY;
        float aw = p3.w * OPACITY;

        c0.x = fmaf(ax, p0.x - c0.x, c0.x);
        c0.y = fmaf(ay, p0.y - c0.y, c0.y);
        c0.z = fmaf(az, p0.z - c0.z, c0.z);
        c0.w = fmaf(aw, p0.w - c0.w, c0.w);

        c1.x = fmaf(ax, p1.x - c1.x, c1.x);
        c1.y = fmaf(ay, p1.y - c1.y, c1.y);
        c1.z = fmaf(az, p1.z - c1.z, c1.z);
        c1.w = fmaf(aw, p1.w - c1.w, c1.w);

        c2.x = fmaf(ax, p2.x - c2.x, c2.x);
        c2.y = fmaf(ay, p2.y - c2.y, c2.y);
        c2.z = fmaf(az, p2.z - c2.z, c2.z);
        c2.w = fmaf(aw, p2.w - c2.w, c2.w);

        c3.x = fmaf(ax, p3.x - c3.x, c3.x);
        c3.y = fmaf(ay, p3.y - c3.y, c3.y);
        c3.z = fmaf(az, p3.z - c3.z, c3.z);
        c3.w = fmaf(aw, p3.w - c3.w, c3.w);

        int nl = l + DEPTH;
        if (nl < NLAYERS)
            issue_layer(nl, slot);
        else
            cp_commit();    // empty group keeps wait_group count aligned

        slot = (slot == DEPTH - 1) ? 0 : slot + 1;
    }

    float4* o = (float4*)(out + q);
    o[0]               = c0;   // chan 0, pixels q..q+3
    *(float4*)(out +     HW + q) = c1;
    *(float4*)(out + 2 * HW + q) = c2;
    *(float4*)(out + 3 * HW + q) = c3;
}

extern "C" void kernel_launch(void* const* d_in, const int* in_sizes, int n_in,
                              void* d_out, int out_size)
{
    const float* polys = (const float*)d_in[0];
    float* out = (float*)d_out;

    const int blocks = HW / 4 / TPB;   // 1024
    painting_kernel<<<blocks, TPB>>>(polys, out);
}